// round 6
// baseline (speedup 1.0000x reference)
#include <cuda_runtime.h>
#include <math.h>

// Problem constants (fixed by the reference)
#define B_FRAMES 256
#define N_COLS   576
#define MR_ROWS  144
#define Z_LIFT   24
#define N_IT     3
#define ROW_DEG  15
#define N_MSG    (MR_ROWS * ROW_DEG)   // 2160
#define NB_A     ((MR_ROWS / Z_LIFT) * (N_COLS / Z_LIFT) * N_IT)  // 432

#define FPB   2                        // frames per CTA
#define BT    512                      // threads per CTA (256 per frame)
#define GRID  (B_FRAMES / FPB)         // 128 CTAs -> 1 per SM, single wave
#define NPASS (MR_ROWS / 16)           // 9 row passes (16-lane groups)

// Sparse graph structure (built from H each launch; no device allocation)
__device__ int g_row_cols[N_MSG];          // CSR: 15 column ids per check row
__device__ int g_col_ptr[N_COLS + 1];      // CSC: per-column edge ranges
__device__ int g_col_edges[N_MSG];         // CSC: edge ids (row-ascending)

// ---------------------------------------------------------------------------
// Kernel 1: extract row structure via warp ballot compaction (one warp/row).
// ---------------------------------------------------------------------------
__global__ void nms_prep_rows(const int* __restrict__ H) {
    int warp = (blockIdx.x * blockDim.x + threadIdx.x) >> 5;
    int lane = threadIdx.x & 31;
    if (warp >= MR_ROWS) return;
    const int* row = H + warp * N_COLS;
    int cnt = 0;
    #pragma unroll
    for (int base = 0; base < N_COLS; base += 32) {
        int v = row[base + lane];
        unsigned ball = __ballot_sync(0xffffffffu, v != 0);
        int before = __popc(ball & ((1u << lane) - 1u));
        if (v != 0) g_row_cols[warp * ROW_DEG + cnt + before] = base + lane;
        cnt += __popc(ball);
    }
}

// ---------------------------------------------------------------------------
// Kernel 2: build the column CSC from g_row_cols. One CTA, 576 threads.
// Count -> block exclusive scan -> atomic scatter -> per-column sort
// (sort makes the edge order, and hence float-sum order, deterministic).
// ---------------------------------------------------------------------------
__global__ void nms_build_csc() {
    __shared__ int s_cnt[N_COLS];
    __shared__ int s_base[N_COLS];
    __shared__ int s_wsum[N_COLS / 32];    // 18 warp sums
    const int tid  = threadIdx.x;          // 0..575
    const int lane = tid & 31;
    const int w    = tid >> 5;

    s_cnt[tid] = 0;
    __syncthreads();
    for (int e = tid; e < N_MSG; e += N_COLS)
        atomicAdd(&s_cnt[g_row_cols[e]], 1);
    __syncthreads();

    // block exclusive scan over the 576 counts
    int v = s_cnt[tid];
    int x = v;
    #pragma unroll
    for (int d = 1; d < 32; d <<= 1) {
        int o = __shfl_up_sync(0xffffffffu, x, d);
        if (lane >= d) x += o;
    }
    if (lane == 31) s_wsum[w] = x;
    __syncthreads();
    if (w == 0 && lane < N_COLS / 32) {
        int y  = s_wsum[lane];
        int yi = y;
        #pragma unroll
        for (int d = 1; d < 32; d <<= 1) {
            int o = __shfl_up_sync(0x3ffffu, yi, d);
            if (lane >= d) yi += o;
        }
        s_wsum[lane] = yi - y;             // exclusive warp offset
    }
    __syncthreads();
    const int excl = x - v + s_wsum[w];    // exclusive prefix for column tid
    g_col_ptr[tid] = excl;
    if (tid == N_COLS - 1) g_col_ptr[N_COLS] = excl + v;
    s_base[tid] = excl;
    __syncthreads();

    // scatter edge ids (order nondeterministic here...)
    for (int e = tid; e < N_MSG; e += N_COLS) {
        int c = g_row_cols[e];
        int pos = atomicAdd(&s_base[c], 1);
        g_col_edges[pos] = e;
    }
    __syncthreads();

    // ...then insertion-sort each column's short list -> deterministic order
    {
        int beg = excl, end = s_base[tid];
        for (int i = beg + 1; i < end; ++i) {
            int key = g_col_edges[i];
            int j = i - 1;
            while (j >= beg && g_col_edges[j] > key) {
                g_col_edges[j + 1] = g_col_edges[j];
                --j;
            }
            g_col_edges[j + 1] = key;
        }
    }
}

// ---------------------------------------------------------------------------
// Kernel 3: decoder. 2 frames/CTA, 16 lanes per check row, NO atomics.
// Per-edge state lives in registers; column sums via CSC gather.
// ---------------------------------------------------------------------------
__global__ __launch_bounds__(BT) void nms_decode(
    const float* __restrict__ r,
    const float* __restrict__ alpha,
    const float* __restrict__ beta,
    float* __restrict__ out)
{
    __shared__ float s_r[FPB][N_COLS];
    __shared__ float s_sumE[FPB][N_COLS];
    __shared__ float s_E[FPB][N_MSG];
    __shared__ float s_a[NB_A];
    __shared__ float s_b[NB_A];
    __shared__ int   s_cp[N_COLS + 1];
    __shared__ int   s_ce[N_MSG];

    const int tid    = threadIdx.x;
    const int f      = tid >> 8;           // frame within CTA
    const int ft     = tid & 255;          // thread id within frame
    const int grp    = ft >> 4;            // 16-lane row group (0..15)
    const int k      = ft & 15;            // edge slot (15 = padding)
    const int b      = blockIdx.x * FPB + f;
    const int lane32 = tid & 31;
    const bool act   = (k < ROW_DEG);
    const unsigned hmask = 0xFFFFu << (lane32 & 16);

    // Stage shared inputs
    for (int i = tid; i < NB_A; i += BT) { s_a[i] = alpha[i]; s_b[i] = beta[i]; }
    for (int i = tid; i <= N_COLS; i += BT) s_cp[i] = g_col_ptr[i];
    for (int i = tid; i < N_MSG; i += BT) s_ce[i] = g_col_edges[i];
    for (int i = ft; i < N_COLS; i += 256) {
        s_r[f][i] = r[b * N_COLS + i];
        s_sumE[f][i] = 0.0f;
    }

    // Per-edge register state (9 edges per thread)
    int   rc[NPASS];                       // column of my edge
    int   aoff[NPASS];                     // alpha/beta base index (per iter +it)
    float rv[NPASS];                       // r[rc]
    float Ep[NPASS];                       // my previous E
    #pragma unroll
    for (int p = 0; p < NPASS; ++p) {
        int row = p * 16 + grp;
        int e = row * ROW_DEG + (act ? k : 0);
        rc[p]   = act ? g_row_cols[e] : 0;
        aoff[p] = (row / Z_LIFT) * ((N_COLS / Z_LIFT) * N_IT)
                + (rc[p] / Z_LIFT) * N_IT;
        Ep[p]   = 0.0f;
    }
    __syncthreads();
    #pragma unroll
    for (int p = 0; p < NPASS; ++p) rv[p] = s_r[f][rc[p]];

    for (int it = 0; it < N_IT; ++it) {
        // ---- check-node phase (edge-parallel, writes s_E) ----
        #pragma unroll
        for (int p = 0; p < NPASS; ++p) {
            float v = rv[p] + s_sumE[f][rc[p]] - Ep[p];   // v->c message
            float av = act ? fabsf(v) : INFINITY;
            unsigned avb = __float_as_uint(av);           // order-preserving (av>=0)

            unsigned negb = __ballot_sync(0xffffffffu, act && (v < 0.0f));
            unsigned zb   = __ballot_sync(0xffffffffu, act && (v == 0.0f));

            unsigned m1 = __reduce_min_sync(hmask, avb);
            unsigned bm = __ballot_sync(0xffffffffu, avb == m1) & hmask;
            const bool leader = (lane32 == (__ffs(bm) - 1));  // argmin (first)
            unsigned avb2 = leader ? 0x7f800000u : avb;
            unsigned m2 = __reduce_min_sync(hmask, avb2);

            if (act) {
                float sel = __uint_as_float(leader ? m2 : m1);
                int   ai  = aoff[p] + it;
                float mag = fmaxf(sel - s_b[ai], 0.0f);
                int parity = __popc(negb & hmask) & 1;
                int neg = parity ^ ((v < 0.0f) ? 1 : 0);
                float E = s_a[ai] * mag;
                E = neg ? -E : E;
                E = (zb & hmask) ? 0.0f : E;              // any zero -> row E = 0
                Ep[p] = E;
                s_E[f][(p * 16 + grp) * ROW_DEG + k] = E;
            }
        }
        __syncthreads();

        // ---- column-sum phase: gather via CSC (no atomics) ----
        for (int i = tid; i < FPB * N_COLS; i += BT) {
            int f2 = i / N_COLS;
            int c  = i - f2 * N_COLS;
            int beg = s_cp[c], end = s_cp[c + 1];
            float s = 0.0f;
            for (int j = beg; j < end; ++j) s += s_E[f2][s_ce[j]];
            s_sumE[f2][c] = s;
        }
        __syncthreads();
    }

    // Posterior LLRs
    for (int i = ft; i < N_COLS; i += 256)
        out[b * N_COLS + i] = s_r[f][i] + s_sumE[f][i];
}

extern "C" void kernel_launch(void* const* d_in, const int* in_sizes, int n_in,
                              void* d_out, int out_size) {
    const float* r     = (const float*)d_in[0];   // (256, 576)
    const float* alpha = (const float*)d_in[1];   // (6, 24, 3)
    const float* beta  = (const float*)d_in[2];   // (6, 24, 3)
    const int*   H     = (const int*)d_in[3];     // (144, 576)
    float* out = (float*)d_out;                   // (256, 576)

    nms_prep_rows<<<18, 256>>>(H);
    nms_build_csc<<<1, N_COLS>>>();
    nms_decode<<<GRID, BT>>>(r, alpha, beta, out);
}